// round 10
// baseline (speedup 1.0000x reference)
#include <cuda_runtime.h>

// Problem constants (fixed by reference_code)
#define NN    48000     // total nodes
#define BB    16        // graphs
#define NPG   3000      // nodes per graph
#define EE    800000    // edges
#define DD    128       // feature dim (all layers)
#define KK    16        // base nodes per graph
#define DCOND 32
#define NC    2

#define NBLK  188       // ceil(NN/256)

// ---------------- device scratch (static, no runtime allocation) ----------------
// NOTE: g_cnt is zero at module load and is re-zeroed by k_scan3 every run,
// so no memset launch is needed and the launch sequence is replay-idempotent.
__device__ float g_bufA[NN * DD];     // 24.6 MB
__device__ float g_bufB[NN * DD];     // 24.6 MB
__device__ int   g_cnt[NN];           // in-degree histogram (self-restoring)
__device__ int   g_off[NN + 1];       // CSR row offsets (by dst)
__device__ int   g_cur[NN];           // scatter cursors
__device__ int   g_csrc[EE];          // CSR src indices
__device__ float g_isq[NN];           // deg^{-1/2} (deg includes self loop)
__device__ int   g_part[NBLK];        // scan partials
__device__ float g_xg[BB * DD];       // global mean pool
__device__ float g_z1[BB * DD];       // lin1 accumulator

// ---------------- f32x2 helpers (packed fp32 pair ops, sm_100+) ----------------
typedef unsigned long long u64t;

__device__ __forceinline__ u64t pk2(float lo, float hi) {
    u64t r; asm("mov.b64 %0, {%1, %2};" : "=l"(r) : "f"(lo), "f"(hi)); return r;
}
__device__ __forceinline__ u64t pkb(float x) {   // broadcast pack
    u64t r; asm("mov.b64 %0, {%1, %1};" : "=l"(r) : "f"(x)); return r;
}
__device__ __forceinline__ void unpk2(u64t v, float& lo, float& hi) {
    asm("mov.b64 {%0, %1}, %2;" : "=f"(lo), "=f"(hi) : "l"(v));
}
__device__ __forceinline__ void ffma2(u64t& d, u64t a, u64t b) {
    asm("fma.rn.f32x2 %0, %1, %2, %0;" : "+l"(d) : "l"(a), "l"(b));
}
__device__ __forceinline__ u64t fadd2(u64t a, u64t b) {
    u64t r; asm("add.rn.f32x2 %0, %1, %2;" : "=l"(r) : "l"(a), "l"(b)); return r;
}

// ---------------- CSR build ----------------
__global__ void k_hist(const int* __restrict__ dst) {
    int e = blockIdx.x * 256 + threadIdx.x;
    if (e < EE) atomicAdd(&g_cnt[dst[e]], 1);
}

__global__ void k_scan1() {   // per-block sums + isq + zero readout accumulators
    __shared__ int sh[256];
    int t = threadIdx.x;
    int i = blockIdx.x * 256 + t;
    int c = (i < NN) ? g_cnt[i] : 0;
    if (i < NN) g_isq[i] = rsqrtf((float)c + 1.0f);
    if (i < BB * DD) { g_z1[i] = 0.f; g_xg[i] = 0.f; }
    sh[t] = c;
    __syncthreads();
    for (int d = 128; d > 0; d >>= 1) {
        if (t < d) sh[t] += sh[t + d];
        __syncthreads();
    }
    if (t == 0) g_part[blockIdx.x] = sh[0];
}

// Fused: each block reduces partials[0..bid) for its base offset, then does
// its local 256-wide exclusive scan. Restores g_cnt to zero for next replay.
__global__ void k_scan3() {
    __shared__ int sh[256];
    __shared__ int base_off;
    int t = threadIdx.x;

    int s = 0;
    for (int p = t; p < blockIdx.x; p += 256) s += g_part[p];
    sh[t] = s;
    __syncthreads();
    for (int d = 128; d > 0; d >>= 1) {
        if (t < d) sh[t] += sh[t + d];
        __syncthreads();
    }
    if (t == 0) base_off = sh[0];
    __syncthreads();

    int i = blockIdx.x * 256 + t;
    int c = (i < NN) ? g_cnt[i] : 0;
    sh[t] = c;
    __syncthreads();
    for (int d = 1; d < 256; d <<= 1) {
        int x = (t >= d) ? sh[t - d] : 0;
        __syncthreads();
        sh[t] += x;
        __syncthreads();
    }
    if (i < NN) {
        int off = base_off + sh[t] - c;
        g_off[i] = off;
        g_cur[i] = off;
        g_cnt[i] = 0;                 // self-restore for next replay
    }
    if (blockIdx.x == 0 && t == 0) g_off[NN] = EE;
}

__global__ void k_scatter(const int* __restrict__ src, const int* __restrict__ dst) {
    int e = blockIdx.x * 256 + threadIdx.x;
    if (e < EE) {
        int d = dst[e];
        int p = atomicAdd(&g_cur[d], 1);
        g_csrc[p] = src[e];
    }
}

// ---------------- GEMM: C[48000,128] = A[48000,128] @ W[128,128] ----------------
// 64-row x 128-col tile, 256 threads, 4x8 register micro-tile via packed f32x2.
// 96 KB smem -> 2 blocks/SM. FFMA2-pipe bound (full fp32 rate).
__global__ void __launch_bounds__(256, 2) k_gemm(const float* __restrict__ A,
                                                 const float* __restrict__ W,
                                                 float* __restrict__ C) {
    extern __shared__ float sh[];
    float* Ws = sh;               // 128*128 = 64 KB
    float* As = sh + DD * DD;     // 64*128  = 32 KB
    int tid = threadIdx.x;
    int row0 = blockIdx.x * 64;

    {   // stage W (4096 float4) and A tile (2048 float4)
        const float4* W4 = (const float4*)W;
        const float4* A4 = (const float4*)(A + (size_t)row0 * DD);
        float4* Ws4 = (float4*)Ws;
        float4* As4 = (float4*)As;
#pragma unroll
        for (int i = 0; i < 16; i++) Ws4[tid + 256 * i] = W4[tid + 256 * i];
#pragma unroll
        for (int i = 0; i < 8; i++)  As4[tid + 256 * i] = A4[tid + 256 * i];
    }
    __syncthreads();

    int tcol = tid & 15;          // 16 col-groups of 8
    int trow = tid >> 4;          // 16 row-groups of 4
    u64t acc[4][4];               // 4 rows x 4 col-pairs (8 cols)
#pragma unroll
    for (int r = 0; r < 4; r++)
#pragma unroll
        for (int c = 0; c < 4; c++) acc[r][c] = 0ull;

    const float* a_base = &As[(trow * 4) * DD];
    const float* w_base = &Ws[tcol * 8];

#pragma unroll 4
    for (int k4 = 0; k4 < DD; k4 += 4) {
        float4 a4[4];
#pragma unroll
        for (int r = 0; r < 4; r++)
            a4[r] = *(const float4*)(a_base + r * DD + k4);
#pragma unroll
        for (int kk = 0; kk < 4; kk++) {
            const float4* wp = (const float4*)(w_base + (k4 + kk) * DD);
            float4 w0 = wp[0];
            float4 w1 = wp[1];
            u64t wv[4];
            wv[0] = pk2(w0.x, w0.y); wv[1] = pk2(w0.z, w0.w);
            wv[2] = pk2(w1.x, w1.y); wv[3] = pk2(w1.z, w1.w);
#pragma unroll
            for (int r = 0; r < 4; r++) {
                float av = (kk == 0) ? a4[r].x : (kk == 1) ? a4[r].y
                         : (kk == 2) ? a4[r].z : a4[r].w;
                u64t ab = pkb(av);
#pragma unroll
                for (int c = 0; c < 4; c++) ffma2(acc[r][c], ab, wv[c]);
            }
        }
    }

#pragma unroll
    for (int r = 0; r < 4; r++) {
        float o[8];
#pragma unroll
        for (int c = 0; c < 4; c++) unpk2(acc[r][c], o[2 * c], o[2 * c + 1]);
        float4* out = (float4*)&C[(size_t)(row0 + trow * 4 + r) * DD + tcol * 8];
        out[0] = make_float4(o[0], o[1], o[2], o[3]);
        out[1] = make_float4(o[4], o[5], o[6], o[7]);
    }
}

// ---------------- Aggregation: 2 warps per dst node (feature-split) ----------------
// Warp pair (node, half): half h covers cols [h*64, h*64+64). Each lane owns 2
// floats (one u64). Doubles warp-level parallelism at ~half the register cost
// of the old layout; per-edge work = 1 LDG.64 + 1 FFMA2.
// out[d] = sum_e hw[src_e]*isq[s]*isq[d] + hw[d]*isq[d]^2 + bias ; optional ReLU
__global__ void __launch_bounds__(256) k_agg(const float* __restrict__ HW,
                                             float* __restrict__ OUT,
                                             const float* __restrict__ bias, int do_relu) {
    int warp = threadIdx.x >> 5;
    int lane = threadIdx.x & 31;
    int node = blockIdx.x * 4 + (warp >> 1);
    int coff = ((warp & 1) << 5) + lane;     // u64 index within the 64-u64 row

    const u64t* hw64 = (const u64t*)HW;
    float isqd = g_isq[node];
    float sc = isqd * isqd;

    // self-loop term
    float slo, shi;
    unpk2(hw64[(size_t)node * 64 + coff], slo, shi);
    u64t acc0 = pk2(slo * sc, shi * sc);
    u64t acc1 = 0ull;

    int e0 = g_off[node], e1 = g_off[node + 1];
    for (int e = e0; e < e1; e += 32) {
        int m = min(32, e1 - e);
        int s = 0; float nn = 0.f;
        if (lane < m) {
            s = g_csrc[e + lane];
            nn = g_isq[s] * isqd;       // g_isq slice is L1-resident (12 KB/graph)
        }
        int j = 0;
        for (; j + 1 < m; j += 2) {
            int   s0 = __shfl_sync(0xffffffffu, s, j);
            int   s1 = __shfl_sync(0xffffffffu, s, j + 1);
            float w0 = __shfl_sync(0xffffffffu, nn, j);
            float w1 = __shfl_sync(0xffffffffu, nn, j + 1);
            u64t v0 = hw64[(size_t)s0 * 64 + coff];
            u64t v1 = hw64[(size_t)s1 * 64 + coff];
            ffma2(acc0, v0, pkb(w0));
            ffma2(acc1, v1, pkb(w1));
        }
        if (j < m) {
            int   s0 = __shfl_sync(0xffffffffu, s, j);
            float w0 = __shfl_sync(0xffffffffu, nn, j);
            u64t v0 = hw64[(size_t)s0 * 64 + coff];
            ffma2(acc0, v0, pkb(w0));
        }
    }
    u64t ra = fadd2(acc0, acc1);
    float rlo, rhi;
    unpk2(ra, rlo, rhi);
    float blo, bhi;
    unpk2(((const u64t*)bias)[coff], blo, bhi);
    rlo += blo; rhi += bhi;
    if (do_relu) { rlo = fmaxf(rlo, 0.f); rhi = fmaxf(rhi, 0.f); }
    ((u64t*)OUT)[(size_t)node * 64 + coff] = pk2(rlo, rhi);
}

// ---------------- Global mean pool: 16 graphs x 8 chunks ----------------
__global__ void k_pool(const float* __restrict__ H) {
    int g = blockIdx.x, ch = blockIdx.y, t = threadIdx.x;
    const float* p = H + ((size_t)g * NPG + ch * (NPG / 8)) * DD + t;
    float s = 0.f;
#pragma unroll 5
    for (int i = 0; i < NPG / 8; i++) s += p[(size_t)i * DD];
    atomicAdd(&g_xg[g * DD + t], s * (1.0f / NPG));
}

// ---------------- lin1: z[16,2176] @ W[2176,128], split over i-dimension ----------------
__global__ void k_lin1(const float* __restrict__ H, const int* __restrict__ base,
                       const float* __restrict__ W1) {
    __shared__ float zsh[BB * 128];   // this block's z slice
    int t = threadIdx.x;
    int i0 = blockIdx.x * 128;        // 17 blocks cover i in [0,2176)

    for (int idx = t; idx < BB * 128; idx += 128) {
        int g = idx >> 7, ii = idx & 127;
        int i = i0 + ii;
        float v;
        if (i < KK * DD) {            // selective gather part x_s
            int k = i >> 7, d = i & 127;
            int bn = base[g * KK + k];
            v = (bn > 0) ? H[((size_t)g * NPG + bn) * DD + d] : 0.f;
        } else {                      // global pool part x_g
            v = g_xg[g * DD + (i - KK * DD)];
        }
        zsh[idx] = v;
    }
    __syncthreads();

    float acc[BB];
#pragma unroll
    for (int g = 0; g < BB; g++) acc[g] = 0.f;
    for (int ii = 0; ii < 128; ii++) {
        float w = W1[(size_t)(i0 + ii) * DD + t];
#pragma unroll
        for (int g = 0; g < BB; g++) acc[g] = fmaf(zsh[g * 128 + ii], w, acc[g]);
    }
#pragma unroll
    for (int g = 0; g < BB; g++) atomicAdd(&g_z1[g * DD + t], acc[g]);
}

// ---------------- final: relu(z1 + b) concat cond -> lin2 -> out[16,2] ----------------
__global__ void k_final(const float* __restrict__ lin1_b, const float* __restrict__ cond,
                        const float* __restrict__ W2, const float* __restrict__ b2,
                        float* __restrict__ out) {
    int t = threadIdx.x;
    if (t >= BB * NC) return;
    int g = t >> 1, c = t & 1;
    float acc = b2[c];
    for (int j = 0; j < DD; j++) {
        float z = fmaxf(g_z1[g * DD + j] + lin1_b[j], 0.f);
        acc = fmaf(z, W2[j * NC + c], acc);
    }
    for (int j = 0; j < DCOND; j++)
        acc = fmaf(cond[g * DCOND + j], W2[(DD + j) * NC + c], acc);
    out[g * NC + c] = acc;
}

// ---------------- launch ----------------
extern "C" void kernel_launch(void* const* d_in, const int* in_sizes, int n_in,
                              void* d_out, int out_size) {
    const float* x      = (const float*)d_in[0];
    const int*   ei     = (const int*)d_in[1];
    const int*   src    = ei;
    const int*   dst    = ei + EE;
    const int*   base   = (const int*)d_in[3];
    const float* cond   = (const float*)d_in[4];
    const float* W[5]   = {(const float*)d_in[5], (const float*)d_in[7],
                           (const float*)d_in[9], (const float*)d_in[11],
                           (const float*)d_in[13]};
    const float* bias[5] = {(const float*)d_in[6], (const float*)d_in[8],
                            (const float*)d_in[10], (const float*)d_in[12],
                            (const float*)d_in[14]};
    const float* lin1_W = (const float*)d_in[15];
    const float* lin1_b = (const float*)d_in[16];
    const float* lin2_W = (const float*)d_in[17];
    const float* lin2_b = (const float*)d_in[18];
    float* out = (float*)d_out;

    // 96 KB dynamic SMEM for the GEMM (idempotent; capture-safe)
    cudaFuncSetAttribute(k_gemm, cudaFuncAttributeMaxDynamicSharedMemorySize, 98304);

    void *pa, *pb;
    cudaGetSymbolAddress(&pa, g_bufA);
    cudaGetSymbolAddress(&pb, g_bufB);
    float* A  = (float*)pa;
    float* Bv = (float*)pb;

    // CSR build (g_cnt zero on entry: zero at load, re-zeroed by k_scan3)
    k_hist<<<EE / 256, 256>>>(dst);
    k_scan1<<<NBLK, 256>>>();
    k_scan3<<<NBLK, 256>>>();
    k_scatter<<<EE / 256, 256>>>(src, dst);

    // 5 GCN layers (ping-pong between g_bufA / g_bufB)
    k_gemm<<<NN / 64, 256, 98304>>>(x, W[0], Bv);
    k_agg<<<NN / 4, 256>>>(Bv, A, bias[0], 1);
    for (int l = 1; l < 5; l++) {
        k_gemm<<<NN / 64, 256, 98304>>>(A, W[l], Bv);
        k_agg<<<NN / 4, 256>>>(Bv, A, bias[l], (l < 4) ? 1 : 0);
    }

    // readout
    k_pool<<<dim3(BB, 8), 128>>>(A);
    k_lin1<<<17, 128>>>(A, base, lin1_W);
    k_final<<<1, 32>>>(lin1_b, cond, lin2_W, lin2_b, out);
}

// round 12
// speedup vs baseline: 1.1289x; 1.1289x over previous
#include <cuda_runtime.h>
#include <cuda_fp16.h>

// Problem constants (fixed by reference_code)
#define NN    48000     // total nodes
#define BB    16        // graphs
#define NPG   3000      // nodes per graph
#define EE    800000    // edges
#define DD    128       // feature dim (all layers)
#define KK    16        // base nodes per graph
#define DCOND 32
#define NC    2

#define NBLK  188       // ceil(NN/256)

// ---------------- device scratch (static, no runtime allocation) ----------------
// g_cnt is zero at module load and re-zeroed by k_scan3 every run (replay-safe).
__device__ float g_bufA[NN * DD];     // fp32 activations (layer input / agg output)
__device__ __half g_bufH[NN * DD];    // fp16 GEMM output (agg gather source), 12.3 MB
__device__ int   g_cnt[NN];           // in-degree histogram (self-restoring)
__device__ int   g_off[NN + 1];       // CSR row offsets (by dst)
__device__ int   g_cur[NN];           // scatter cursors
__device__ int   g_csrc[EE];          // CSR src indices
__device__ float g_isq[NN];           // deg^{-1/2} (deg includes self loop)
__device__ int   g_part[NBLK];        // scan partials
__device__ float g_xg[BB * DD];       // global mean pool
__device__ float g_z1[BB * DD];       // lin1 accumulator

// ---------------- f32x2 / f16x2 helpers ----------------
typedef unsigned long long u64t;

__device__ __forceinline__ u64t pk2(float lo, float hi) {
    u64t r; asm("mov.b64 %0, {%1, %2};" : "=l"(r) : "f"(lo), "f"(hi)); return r;
}
__device__ __forceinline__ u64t pkb(float x) {   // broadcast pack
    u64t r; asm("mov.b64 %0, {%1, %1};" : "=l"(r) : "f"(x)); return r;
}
__device__ __forceinline__ void unpk2(u64t v, float& lo, float& hi) {
    asm("mov.b64 {%0, %1}, %2;" : "=f"(lo), "=f"(hi) : "l"(v));
}
__device__ __forceinline__ void ffma2(u64t& d, u64t a, u64t b) {
    asm("fma.rn.f32x2 %0, %1, %2, %0;" : "+l"(d) : "l"(a), "l"(b));
}
__device__ __forceinline__ u64t fadd2(u64t a, u64t b) {
    u64t r; asm("add.rn.f32x2 %0, %1, %2;" : "=l"(r) : "l"(a), "l"(b)); return r;
}
// pack two fp32 -> fp16x2 (lo = first arg)
__device__ __forceinline__ unsigned int pkh2(float lo, float hi) {
    unsigned int r;
    asm("cvt.rn.f16x2.f32 %0, %1, %2;" : "=r"(r) : "f"(hi), "f"(lo));
    return r;
}

// ---------------- CSR build ----------------
__global__ void k_hist(const int* __restrict__ dst) {
    int e = blockIdx.x * 256 + threadIdx.x;
    if (e < EE) atomicAdd(&g_cnt[dst[e]], 1);
}

__global__ void k_scan1() {   // per-block sums + isq + zero readout accumulators
    __shared__ int sh[256];
    int t = threadIdx.x;
    int i = blockIdx.x * 256 + t;
    int c = (i < NN) ? g_cnt[i] : 0;
    if (i < NN) g_isq[i] = rsqrtf((float)c + 1.0f);
    if (i < BB * DD) { g_z1[i] = 0.f; g_xg[i] = 0.f; }
    sh[t] = c;
    __syncthreads();
    for (int d = 128; d > 0; d >>= 1) {
        if (t < d) sh[t] += sh[t + d];
        __syncthreads();
    }
    if (t == 0) g_part[blockIdx.x] = sh[0];
}

// Fused: block reduces partials[0..bid) for base offset, then local scan.
// Restores g_cnt to zero for the next replay.
__global__ void k_scan3() {
    __shared__ int sh[256];
    __shared__ int base_off;
    int t = threadIdx.x;

    int s = 0;
    for (int p = t; p < blockIdx.x; p += 256) s += g_part[p];
    sh[t] = s;
    __syncthreads();
    for (int d = 128; d > 0; d >>= 1) {
        if (t < d) sh[t] += sh[t + d];
        __syncthreads();
    }
    if (t == 0) base_off = sh[0];
    __syncthreads();

    int i = blockIdx.x * 256 + t;
    int c = (i < NN) ? g_cnt[i] : 0;
    sh[t] = c;
    __syncthreads();
    for (int d = 1; d < 256; d <<= 1) {
        int x = (t >= d) ? sh[t - d] : 0;
        __syncthreads();
        sh[t] += x;
        __syncthreads();
    }
    if (i < NN) {
        int off = base_off + sh[t] - c;
        g_off[i] = off;
        g_cur[i] = off;
        g_cnt[i] = 0;                 // self-restore for next replay
    }
    if (blockIdx.x == 0 && t == 0) g_off[NN] = EE;
}

__global__ void k_scatter(const int* __restrict__ src, const int* __restrict__ dst) {
    int e = blockIdx.x * 256 + threadIdx.x;
    if (e < EE) {
        int d = dst[e];
        int p = atomicAdd(&g_cur[d], 1);
        g_csrc[p] = src[e];
    }
}

// ---------------- GEMM: H[48000,128] fp16 = A[48000,128] fp32 @ W[128,128] ----------------
// 64-row x 128-col tile, 256 threads, 4x8 register micro-tile via packed f32x2.
// 96 KB smem -> 2 blocks/SM. FFMA2-pipe bound. Output packed fp16 (halves agg traffic).
__global__ void __launch_bounds__(256, 2) k_gemm(const float* __restrict__ A,
                                                 const float* __restrict__ W,
                                                 __half* __restrict__ C) {
    extern __shared__ float sh[];
    float* Ws = sh;               // 128*128 = 64 KB
    float* As = sh + DD * DD;     // 64*128  = 32 KB
    int tid = threadIdx.x;
    int row0 = blockIdx.x * 64;

    {   // stage W (4096 float4) and A tile (2048 float4)
        const float4* W4 = (const float4*)W;
        const float4* A4 = (const float4*)(A + (size_t)row0 * DD);
        float4* Ws4 = (float4*)Ws;
        float4* As4 = (float4*)As;
#pragma unroll
        for (int i = 0; i < 16; i++) Ws4[tid + 256 * i] = W4[tid + 256 * i];
#pragma unroll
        for (int i = 0; i < 8; i++)  As4[tid + 256 * i] = A4[tid + 256 * i];
    }
    __syncthreads();

    int tcol = tid & 15;          // 16 col-groups of 8
    int trow = tid >> 4;          // 16 row-groups of 4
    u64t acc[4][4];               // 4 rows x 4 col-pairs (8 cols)
#pragma unroll
    for (int r = 0; r < 4; r++)
#pragma unroll
        for (int c = 0; c < 4; c++) acc[r][c] = 0ull;

    const float* a_base = &As[(trow * 4) * DD];
    const float* w_base = &Ws[tcol * 8];

#pragma unroll 4
    for (int k4 = 0; k4 < DD; k4 += 4) {
        float4 a4[4];
#pragma unroll
        for (int r = 0; r < 4; r++)
            a4[r] = *(const float4*)(a_base + r * DD + k4);
#pragma unroll
        for (int kk = 0; kk < 4; kk++) {
            const float4* wp = (const float4*)(w_base + (k4 + kk) * DD);
            float4 w0 = wp[0];
            float4 w1 = wp[1];
            u64t wv[4];
            wv[0] = pk2(w0.x, w0.y); wv[1] = pk2(w0.z, w0.w);
            wv[2] = pk2(w1.x, w1.y); wv[3] = pk2(w1.z, w1.w);
#pragma unroll
            for (int r = 0; r < 4; r++) {
                float av = (kk == 0) ? a4[r].x : (kk == 1) ? a4[r].y
                         : (kk == 2) ? a4[r].z : a4[r].w;
                u64t ab = pkb(av);
#pragma unroll
                for (int c = 0; c < 4; c++) ffma2(acc[r][c], ab, wv[c]);
            }
        }
    }

#pragma unroll
    for (int r = 0; r < 4; r++) {
        float o[8];
#pragma unroll
        for (int c = 0; c < 4; c++) unpk2(acc[r][c], o[2 * c], o[2 * c + 1]);
        uint4 st;
        st.x = pkh2(o[0], o[1]);
        st.y = pkh2(o[2], o[3]);
        st.z = pkh2(o[4], o[5]);
        st.w = pkh2(o[6], o[7]);
        *(uint4*)&C[(size_t)(row0 + trow * 4 + r) * DD + tcol * 8] = st;
    }
}

// ---------------- Aggregation: warp per dst node, fp16 gather ----------------
// out[d] = sum_e hw[src_e]*isq[s]*isq[d] + hw[d]*isq[d]^2 + bias ; optional ReLU
// Gather source is fp16 (8 B/lane, 256 B/row) -> half the L2 traffic of fp32.
// Structure = proven R6 shape: warp/node, 128 thr, 2-way unroll, fp32 accum.
__global__ void __launch_bounds__(128) k_agg(const __half* __restrict__ HW,
                                             float* __restrict__ OUT,
                                             const float* __restrict__ bias, int do_relu) {
    int warp = threadIdx.x >> 5;
    int lane = threadIdx.x & 31;
    int node = blockIdx.x * 4 + warp;

    const uint2* hw = (const uint2*)HW;   // 4 halves per lane, 32 lanes = 256 B/row
    float isqd = g_isq[node];
    float sc = isqd * isqd;

    // self-loop term
    uint2 sv = hw[(size_t)node * 32 + lane];
    float2 s01 = __half22float2(*(const __half2*)&sv.x);
    float2 s23 = __half22float2(*(const __half2*)&sv.y);
    u64t acc0a = pk2(s01.x * sc, s01.y * sc);
    u64t acc0b = pk2(s23.x * sc, s23.y * sc);
    u64t acc1a = 0ull, acc1b = 0ull;

    int e0 = g_off[node], e1 = g_off[node + 1];
    for (int e = e0; e < e1; e += 32) {
        int m = min(32, e1 - e);
        int s = 0; float nn = 0.f;
        if (lane < m) {
            s = g_csrc[e + lane];
            nn = g_isq[s] * isqd;       // g_isq slice is L1-resident (12 KB/graph)
        }
        int j = 0;
        for (; j + 1 < m; j += 2) {
            int   s0 = __shfl_sync(0xffffffffu, s, j);
            int   s1 = __shfl_sync(0xffffffffu, s, j + 1);
            float w0 = __shfl_sync(0xffffffffu, nn, j);
            float w1 = __shfl_sync(0xffffffffu, nn, j + 1);
            uint2 v0 = hw[(size_t)s0 * 32 + lane];
            uint2 v1 = hw[(size_t)s1 * 32 + lane];
            float2 a01 = __half22float2(*(const __half2*)&v0.x);
            float2 a23 = __half22float2(*(const __half2*)&v0.y);
            float2 b01 = __half22float2(*(const __half2*)&v1.x);
            float2 b23 = __half22float2(*(const __half2*)&v1.y);
            u64t wb0 = pkb(w0), wb1 = pkb(w1);
            ffma2(acc0a, pk2(a01.x, a01.y), wb0);
            ffma2(acc0b, pk2(a23.x, a23.y), wb0);
            ffma2(acc1a, pk2(b01.x, b01.y), wb1);
            ffma2(acc1b, pk2(b23.x, b23.y), wb1);
        }
        if (j < m) {
            int   s0 = __shfl_sync(0xffffffffu, s, j);
            float w0 = __shfl_sync(0xffffffffu, nn, j);
            uint2 v0 = hw[(size_t)s0 * 32 + lane];
            float2 a01 = __half22float2(*(const __half2*)&v0.x);
            float2 a23 = __half22float2(*(const __half2*)&v0.y);
            u64t wb0 = pkb(w0);
            ffma2(acc0a, pk2(a01.x, a01.y), wb0);
            ffma2(acc0b, pk2(a23.x, a23.y), wb0);
        }
    }
    u64t ra = fadd2(acc0a, acc1a);
    u64t rb = fadd2(acc0b, acc1b);
    float4 r;
    unpk2(ra, r.x, r.y);
    unpk2(rb, r.z, r.w);
    float4 bv = ((const float4*)bias)[lane];
    r.x += bv.x; r.y += bv.y; r.z += bv.z; r.w += bv.w;
    if (do_relu) {
        r.x = fmaxf(r.x, 0.f); r.y = fmaxf(r.y, 0.f);
        r.z = fmaxf(r.z, 0.f); r.w = fmaxf(r.w, 0.f);
    }
    ((float4*)OUT)[(size_t)node * 32 + lane] = r;
}

// ---------------- Global mean pool: 16 graphs x 8 chunks ----------------
__global__ void k_pool(const float* __restrict__ H) {
    int g = blockIdx.x, ch = blockIdx.y, t = threadIdx.x;
    const float* p = H + ((size_t)g * NPG + ch * (NPG / 8)) * DD + t;
    float s = 0.f;
#pragma unroll 5
    for (int i = 0; i < NPG / 8; i++) s += p[(size_t)i * DD];
    atomicAdd(&g_xg[g * DD + t], s * (1.0f / NPG));
}

// ---------------- lin1: z[16,2176] @ W[2176,128], split over i-dimension ----------------
__global__ void k_lin1(const float* __restrict__ H, const int* __restrict__ base,
                       const float* __restrict__ W1) {
    __shared__ float zsh[BB * 128];   // this block's z slice
    int t = threadIdx.x;
    int i0 = blockIdx.x * 128;        // 17 blocks cover i in [0,2176)

    for (int idx = t; idx < BB * 128; idx += 128) {
        int g = idx >> 7, ii = idx & 127;
        int i = i0 + ii;
        float v;
        if (i < KK * DD) {            // selective gather part x_s
            int k = i >> 7, d = i & 127;
            int bn = base[g * KK + k];
            v = (bn > 0) ? H[((size_t)g * NPG + bn) * DD + d] : 0.f;
        } else {                      // global pool part x_g
            v = g_xg[g * DD + (i - KK * DD)];
        }
        zsh[idx] = v;
    }
    __syncthreads();

    float acc[BB];
#pragma unroll
    for (int g = 0; g < BB; g++) acc[g] = 0.f;
    for (int ii = 0; ii < 128; ii++) {
        float w = W1[(size_t)(i0 + ii) * DD + t];
#pragma unroll
        for (int g = 0; g < BB; g++) acc[g] = fmaf(zsh[g * 128 + ii], w, acc[g]);
    }
#pragma unroll
    for (int g = 0; g < BB; g++) atomicAdd(&g_z1[g * DD + t], acc[g]);
}

// ---------------- final: relu(z1 + b) concat cond -> lin2 -> out[16,2] ----------------
__global__ void k_final(const float* __restrict__ lin1_b, const float* __restrict__ cond,
                        const float* __restrict__ W2, const float* __restrict__ b2,
                        float* __restrict__ out) {
    int t = threadIdx.x;
    if (t >= BB * NC) return;
    int g = t >> 1, c = t & 1;
    float acc = b2[c];
    for (int j = 0; j < DD; j++) {
        float z = fmaxf(g_z1[g * DD + j] + lin1_b[j], 0.f);
        acc = fmaf(z, W2[j * NC + c], acc);
    }
    for (int j = 0; j < DCOND; j++)
        acc = fmaf(cond[g * DCOND + j], W2[(DD + j) * NC + c], acc);
    out[g * NC + c] = acc;
}

// ---------------- launch ----------------
extern "C" void kernel_launch(void* const* d_in, const int* in_sizes, int n_in,
                              void* d_out, int out_size) {
    const float* x      = (const float*)d_in[0];
    const int*   ei     = (const int*)d_in[1];
    const int*   src    = ei;
    const int*   dst    = ei + EE;
    const int*   base   = (const int*)d_in[3];
    const float* cond   = (const float*)d_in[4];
    const float* W[5]   = {(const float*)d_in[5], (const float*)d_in[7],
                           (const float*)d_in[9], (const float*)d_in[11],
                           (const float*)d_in[13]};
    const float* bias[5] = {(const float*)d_in[6], (const float*)d_in[8],
                            (const float*)d_in[10], (const float*)d_in[12],
                            (const float*)d_in[14]};
    const float* lin1_W = (const float*)d_in[15];
    const float* lin1_b = (const float*)d_in[16];
    const float* lin2_W = (const float*)d_in[17];
    const float* lin2_b = (const float*)d_in[18];
    float* out = (float*)d_out;

    // 96 KB dynamic SMEM for the GEMM (idempotent; capture-safe)
    cudaFuncSetAttribute(k_gemm, cudaFuncAttributeMaxDynamicSharedMemorySize, 98304);

    void *pa, *ph;
    cudaGetSymbolAddress(&pa, g_bufA);
    cudaGetSymbolAddress(&ph, g_bufH);
    float*  A = (float*)pa;
    __half* H = (__half*)ph;

    // CSR build (g_cnt zero on entry: zero at load, re-zeroed by k_scan3)
    k_hist<<<EE / 256, 256>>>(dst);
    k_scan1<<<NBLK, 256>>>();
    k_scan3<<<NBLK, 256>>>();
    k_scatter<<<EE / 256, 256>>>(src, dst);

    // 5 GCN layers: gemm (fp32 in -> fp16 out), agg (fp16 gather -> fp32 out)
    k_gemm<<<NN / 64, 256, 98304>>>(x, W[0], H);
    k_agg<<<NN / 4, 128>>>(H, A, bias[0], 1);
    for (int l = 1; l < 5; l++) {
        k_gemm<<<NN / 64, 256, 98304>>>(A, W[l], H);
        k_agg<<<NN / 4, 128>>>(H, A, bias[l], (l < 4) ? 1 : 0);
    }

    // readout
    k_pool<<<dim3(BB, 8), 128>>>(A);
    k_lin1<<<17, 128>>>(A, base, lin1_W);
    k_final<<<1, 32>>>(lin1_b, cond, lin2_W, lin2_b, out);
}